// round 13
// baseline (speedup 1.0000x reference)
#include <cuda_runtime.h>
#include <math.h>
#include <stdint.h>

#define EMB 1024
#define SEQ 1024
#define NB 8
#define HEADS 16
#define HD 64
#define ROWS (NB * SEQ)                  // 8192
#define OUT_ELEMS ((size_t)ROWS * EMB)   // 8388608
#define SROW 20                          // smem words per row (80B, 16B-aligned)
#define NCB (SEQ / 128)                  // 8 col-blocks per attention row

// Scratch (static device globals; no runtime allocation allowed)
__device__ float g_Q[ROWS * EMB];
__device__ float g_K[ROWS * EMB];
__device__ float g_V[ROWS * EMB];
__device__ float g_O[ROWS * EMB];
__device__ float g_smax[(size_t)NB * HEADS * SEQ * NCB];   // per-block row max
__device__ float g_ssum[(size_t)NB * HEADS * SEQ * NCB];   // per-block row expsum

// ---------------------------------------------------------------------------
// helpers
// ---------------------------------------------------------------------------
__device__ __forceinline__ unsigned f2tf(float x) {
    unsigned r;
    asm("cvt.rna.tf32.f32 %0, %1;" : "=r"(r) : "f"(x));
    return r;
}

__device__ __forceinline__ void mma_tf32(float* c, const unsigned* a, const unsigned* b) {
    asm volatile(
        "mma.sync.aligned.m16n8k8.row.col.f32.tf32.tf32.f32 "
        "{%0,%1,%2,%3},{%4,%5,%6,%7},{%8,%9},{%0,%1,%2,%3};\n"
        : "+f"(c[0]), "+f"(c[1]), "+f"(c[2]), "+f"(c[3])
        : "r"(a[0]), "r"(a[1]), "r"(a[2]), "r"(a[3]),
          "r"(b[0]), "r"(b[1]));
}

__device__ __forceinline__ uint32_t smem_u32(const void* p) {
    uint32_t a;
    asm("{ .reg .u64 t; cvta.to.shared.u64 t, %1; cvt.u32.u64 %0, t; }"
        : "=r"(a) : "l"(p));
    return a;
}

__device__ __forceinline__ void ldsm4(unsigned& r0, unsigned& r1, unsigned& r2,
                                      unsigned& r3, uint32_t addr) {
    asm volatile("ldmatrix.sync.aligned.m8n8.x4.shared.b16 {%0,%1,%2,%3}, [%4];"
                 : "=r"(r0), "=r"(r1), "=r"(r2), "=r"(r3) : "r"(addr));
}

// byte offset of the 16B chunk jc (tf32 cols jc*4..jc*4+3) of row `row`
__device__ __forceinline__ uint32_t frag_off(int row, int jc) {
    const int chunk = jc ^ ((row >> 3) & 3);
    return (uint32_t)((row * SROW + chunk * 4) * 4);
}

// ---------------------------------------------------------------------------
// NT GEMM: C = alpha * A(row-major,lda) @ B(row-major,ldb)^T + bias
// CTA 128x128, 128 thr (4 warps), warp tile 64x64, BK=16 double-buffered.
// ---------------------------------------------------------------------------
template <int KDIM>
__device__ __forceinline__ void gemm_nt_body(
    const float* __restrict__ A, int lda,
    const float* __restrict__ B, int ldb,
    float* __restrict__ C, int ldc,
    float alpha, const float* __restrict__ bias)
{
    __shared__ unsigned As[2][128 * SROW];
    __shared__ unsigned Bs[2][128 * SROW];

    const int tid  = threadIdx.x;
    const int m0   = blockIdx.y * 128;
    const int n0   = blockIdx.x * 128;
    const int warp = tid >> 5;
    const int lane = tid & 31;
    const int wr   = (warp >> 1) * 64;
    const int wc   = (warp & 1) * 64;
    const int g    = lane >> 2;
    const int t    = lane & 3;

    const uint32_t abase[2] = { smem_u32(&As[0][0]), smem_u32(&As[1][0]) };
    const uint32_t bbase[2] = { smem_u32(&Bs[0][0]), smem_u32(&Bs[1][0]) };

    const int lrow8 = ((lane >> 3) & 1) * 8 + (lane & 7);
    const int ljc   = lane >> 4;
    uint32_t aoff[2][4], boff[2][4];
#pragma unroll
    for (int kkc = 0; kkc < 2; kkc++)
#pragma unroll
        for (int i = 0; i < 4; i++) {
            aoff[kkc][i] = frag_off(wr + i * 16 + lrow8, kkc * 2 + ljc);
            boff[kkc][i] = frag_off(wc + i * 16 + lrow8, kkc * 2 + ljc);
        }

    float acc[4][8][4] = {};

    const int srow = tid;
    const float* Ap = A + (size_t)(m0 + srow) * lda;
    const float* Bp = B + (size_t)(n0 + srow) * ldb;
    const int schunkx = (srow >> 3) & 3;

    float4 av[4], bv[4];
    auto ldtile = [&](int kt) {
#pragma unroll
        for (int j = 0; j < 4; j++) {
            av[j] = *(const float4*)(Ap + kt * 16 + j * 4);
            bv[j] = *(const float4*)(Bp + kt * 16 + j * 4);
        }
    };
    auto sttile = [&](int buf) {
#pragma unroll
        for (int j = 0; j < 4; j++) {
            const int chunk = j ^ schunkx;
            uint4 at = make_uint4(f2tf(av[j].x), f2tf(av[j].y), f2tf(av[j].z), f2tf(av[j].w));
            uint4 bt = make_uint4(f2tf(bv[j].x), f2tf(bv[j].y), f2tf(bv[j].z), f2tf(bv[j].w));
            *(uint4*)&As[buf][srow * SROW + chunk * 4] = at;
            *(uint4*)&Bs[buf][srow * SROW + chunk * 4] = bt;
        }
    };

    ldtile(0);
    sttile(0);
    __syncthreads();

    const int NT = KDIM / 16;
#pragma unroll 1
    for (int kt = 0; kt < NT; kt++) {
        const int buf = kt & 1;
        if (kt + 1 < NT) ldtile(kt + 1);

#pragma unroll
        for (int kkc = 0; kkc < 2; kkc++) {
            unsigned af[4][4], bf[8][2];
#pragma unroll
            for (int mi = 0; mi < 4; mi++)
                ldsm4(af[mi][0], af[mi][1], af[mi][2], af[mi][3],
                      abase[buf] + aoff[kkc][mi]);
#pragma unroll
            for (int p = 0; p < 4; p++) {
                unsigned r0, r1, r2, r3;
                ldsm4(r0, r1, r2, r3, bbase[buf] + boff[kkc][p]);
                bf[2 * p][0] = r0; bf[2 * p + 1][0] = r1;
                bf[2 * p][1] = r2; bf[2 * p + 1][1] = r3;
            }
#pragma unroll
            for (int mi = 0; mi < 4; mi++)
#pragma unroll
                for (int ni = 0; ni < 8; ni++)
                    mma_tf32(acc[mi][ni], af[mi], bf[ni]);
        }

        if (kt + 1 < NT) sttile(buf ^ 1);
        __syncthreads();
    }

#pragma unroll
    for (int mi = 0; mi < 4; mi++) {
#pragma unroll
        for (int ni = 0; ni < 8; ni++) {
            const int row = m0 + wr + mi * 16 + g;
            const int col = n0 + wc + ni * 8 + t * 2;
            float b0 = 0.f, b1 = 0.f;
            if (bias) { b0 = bias[col]; b1 = bias[col + 1]; }
            *(float2*)&C[(size_t)row * ldc + col] =
                make_float2(acc[mi][ni][0] * alpha + b0, acc[mi][ni][1] * alpha + b1);
            *(float2*)&C[(size_t)(row + 8) * ldc + col] =
                make_float2(acc[mi][ni][2] * alpha + b0, acc[mi][ni][3] * alpha + b1);
        }
    }
}

// Fused Q/K/V projections: grid.z selects which GEMM.
__global__ __launch_bounds__(128, 2) void qkv_proj(
    const float* __restrict__ query, const float* __restrict__ key_,
    const float* __restrict__ value,
    const float* __restrict__ Wq, const float* __restrict__ Wk,
    const float* __restrict__ Wv)
{
    const int z = blockIdx.z;
    const float* A = (z == 0) ? query : (z == 1) ? key_ : value;
    const float* W = (z == 0) ? Wq : (z == 1) ? Wk : Wv;
    float* C = (z == 0) ? g_Q : (z == 1) ? g_K : g_V;
    gemm_nt_body<EMB>(A, EMB, W, EMB, C, EMB, 1.0f, nullptr);
}

__global__ __launch_bounds__(128, 2) void proj_tf32(
    const float* __restrict__ A, const float* __restrict__ B,
    float* __restrict__ C, const float* __restrict__ bias)
{
    gemm_nt_body<EMB>(A, EMB, B, EMB, C, EMB, 1.0f, bias);
}

// ---------------------------------------------------------------------------
// energy + per-tile row softmax stats.
// E[z,q,k] = 0.125 * Q.K ; also writes per (row, colblock): masked row max and
// expsum into g_smax/g_ssum. grid=(8,8,128).
// ---------------------------------------------------------------------------
__global__ __launch_bounds__(128, 2) void energy_stats(
    float* __restrict__ att, const int* __restrict__ mask)
{
    const int z = blockIdx.z;
    const int n = z >> 4, h = z & 15;
    const float* A = g_Q + (size_t)n * SEQ * EMB + h * HD;
    const float* B = g_K + (size_t)n * SEQ * EMB + h * HD;
    float* C = att + (size_t)z * SEQ * SEQ;
    const int* mrow = mask + n * SEQ;

    __shared__ unsigned As[2][128 * SROW];
    __shared__ unsigned Bs[2][128 * SROW];
    __shared__ float sm_max[128][2];
    __shared__ float sm_sum[128][2];

    const int tid  = threadIdx.x;
    const int m0   = blockIdx.y * 128;
    const int n0   = blockIdx.x * 128;
    const int warp = tid >> 5;
    const int lane = tid & 31;
    const int wr   = (warp >> 1) * 64;
    const int wc   = (warp & 1) * 64;
    const int g    = lane >> 2;
    const int t    = lane & 3;

    const uint32_t abase[2] = { smem_u32(&As[0][0]), smem_u32(&As[1][0]) };
    const uint32_t bbase[2] = { smem_u32(&Bs[0][0]), smem_u32(&Bs[1][0]) };

    const int lrow8 = ((lane >> 3) & 1) * 8 + (lane & 7);
    const int ljc   = lane >> 4;
    uint32_t aoff[2][4], boff[2][4];
#pragma unroll
    for (int kkc = 0; kkc < 2; kkc++)
#pragma unroll
        for (int i = 0; i < 4; i++) {
            aoff[kkc][i] = frag_off(wr + i * 16 + lrow8, kkc * 2 + ljc);
            boff[kkc][i] = frag_off(wc + i * 16 + lrow8, kkc * 2 + ljc);
        }

    float acc[4][8][4] = {};

    const int srow = tid;
    const float* Ap = A + (size_t)(m0 + srow) * EMB;
    const float* Bp = B + (size_t)(n0 + srow) * EMB;
    const int schunkx = (srow >> 3) & 3;

    float4 av[4], bv[4];
    auto ldtile = [&](int kt) {
#pragma unroll
        for (int j = 0; j < 4; j++) {
            av[j] = *(const float4*)(Ap + kt * 16 + j * 4);
            bv[j] = *(const float4*)(Bp + kt * 16 + j * 4);
        }
    };
    auto sttile = [&](int buf) {
#pragma unroll
        for (int j = 0; j < 4; j++) {
            const int chunk = j ^ schunkx;
            uint4 at = make_uint4(f2tf(av[j].x), f2tf(av[j].y), f2tf(av[j].z), f2tf(av[j].w));
            uint4 bt = make_uint4(f2tf(bv[j].x), f2tf(bv[j].y), f2tf(bv[j].z), f2tf(bv[j].w));
            *(uint4*)&As[buf][srow * SROW + chunk * 4] = at;
            *(uint4*)&Bs[buf][srow * SROW + chunk * 4] = bt;
        }
    };

    ldtile(0);
    sttile(0);
    __syncthreads();

    const int NT = HD / 16;
#pragma unroll 1
    for (int kt = 0; kt < NT; kt++) {
        const int buf = kt & 1;
        if (kt + 1 < NT) ldtile(kt + 1);

#pragma unroll
        for (int kkc = 0; kkc < 2; kkc++) {
            unsigned af[4][4], bf[8][2];
#pragma unroll
            for (int mi = 0; mi < 4; mi++)
                ldsm4(af[mi][0], af[mi][1], af[mi][2], af[mi][3],
                      abase[buf] + aoff[kkc][mi]);
#pragma unroll
            for (int p = 0; p < 4; p++) {
                unsigned r0, r1, r2, r3;
                ldsm4(r0, r1, r2, r3, bbase[buf] + boff[kkc][p]);
                bf[2 * p][0] = r0; bf[2 * p + 1][0] = r1;
                bf[2 * p][1] = r2; bf[2 * p + 1][1] = r3;
            }
#pragma unroll
            for (int mi = 0; mi < 4; mi++)
#pragma unroll
                for (int ni = 0; ni < 8; ni++)
                    mma_tf32(acc[mi][ni], af[mi], bf[ni]);
        }

        if (kt + 1 < NT) sttile(buf ^ 1);
        __syncthreads();
    }

    // store raw E + compute masked row stats for this 128-col block
    int mk[8][2];
#pragma unroll
    for (int ni = 0; ni < 8; ni++) {
        const int col = n0 + wc + ni * 8 + t * 2;
        mk[ni][0] = mrow[col];
        mk[ni][1] = mrow[col + 1];
    }

#pragma unroll
    for (int mi = 0; mi < 4; mi++) {
#pragma unroll
        for (int ni = 0; ni < 8; ni++) {
            const int row = m0 + wr + mi * 16 + g;
            const int col = n0 + wc + ni * 8 + t * 2;
            *(float2*)&C[(size_t)row * SEQ + col] =
                make_float2(acc[mi][ni][0] * 0.125f, acc[mi][ni][1] * 0.125f);
            *(float2*)&C[(size_t)(row + 8) * SEQ + col] =
                make_float2(acc[mi][ni][2] * 0.125f, acc[mi][ni][3] * 0.125f);
        }
    }

#pragma unroll
    for (int mi = 0; mi < 4; mi++) {
#pragma unroll
        for (int half = 0; half < 2; half++) {
            float v[8][2];
            float vmax = -3.4e38f;
#pragma unroll
            for (int ni = 0; ni < 8; ni++) {
#pragma unroll
                for (int j = 0; j < 2; j++) {
                    float x = acc[mi][ni][half * 2 + j] * 0.125f;
                    if (mk[ni][j] == 0) x = -1e20f;
                    v[ni][j] = x;
                    vmax = fmaxf(vmax, x);
                }
            }
            vmax = fmaxf(vmax, __shfl_xor_sync(0xffffffffu, vmax, 1));
            vmax = fmaxf(vmax, __shfl_xor_sync(0xffffffffu, vmax, 2));
            float s = 0.f;
#pragma unroll
            for (int ni = 0; ni < 8; ni++)
                s += __expf(v[ni][0] - vmax) + __expf(v[ni][1] - vmax);
            s += __shfl_xor_sync(0xffffffffu, s, 1);
            s += __shfl_xor_sync(0xffffffffu, s, 2);
            if (t == 0) {
                const int r = wr + mi * 16 + g + half * 8;
                sm_max[r][warp & 1] = vmax;
                sm_sum[r][warp & 1] = s;
            }
        }
    }
    __syncthreads();

    {
        const float a0 = sm_max[tid][0], a1 = sm_max[tid][1];
        const float M = fmaxf(a0, a1);
        const float S = sm_sum[tid][0] * __expf(a0 - M) + sm_sum[tid][1] * __expf(a1 - M);
        const size_t idx = ((size_t)z * SEQ + m0 + tid) * NCB + blockIdx.x;
        g_smax[idx] = M;
        g_ssum[idx] = S;
    }
}

// ---------------------------------------------------------------------------
// Fused softmax + att@V: per z, C[128,64] tile = P[128,1024] @ V[1024,64].
// Row stats combined from g_smax/g_ssum; staging converts raw E -> P,
// writes P (final attention output, streaming) and feeds the MMAs.
// ---------------------------------------------------------------------------
__global__ __launch_bounds__(128, 2) void attv_fused(
    float* __restrict__ att, const int* __restrict__ mask)
{
    const int z = blockIdx.z;
    const int n = z >> 4, h = z & 15;
    float* A = att + (size_t)z * SEQ * SEQ;          // raw E in, P out
    const float* B = g_V + (size_t)n * SEQ * EMB + h * HD;
    float* C = g_O + (size_t)n * SEQ * EMB + h * HD;
    const int* mrow = mask + n * SEQ;

    __shared__ unsigned As[2][128 * SROW];
    __shared__ unsigned Bs[2][64 * SROW];
    __shared__ float sm_m[128];
    __shared__ float sm_li[128];

    const int tid  = threadIdx.x;
    const int m0   = blockIdx.y * 128;
    const int warp = tid >> 5;
    const int lane = tid & 31;
    const int wr   = (warp >> 1) * 64;
    const int wc   = (warp & 1) * 32;
    const int g    = lane >> 2;
    const int t    = lane & 3;

    // ---- combine per-block stats into global (M, 1/l) per row ----
    {
        const size_t sidx = ((size_t)z * SEQ + m0 + tid) * NCB;
        float mb[NCB], sb[NCB];
#pragma unroll
        for (int cb = 0; cb < NCB; cb++) { mb[cb] = g_smax[sidx + cb]; sb[cb] = g_ssum[sidx + cb]; }
        float M = mb[0];
#pragma unroll
        for (int cb = 1; cb < NCB; cb++) M = fmaxf(M, mb[cb]);
        float S = 0.f;
#pragma unroll
        for (int cb = 0; cb < NCB; cb++) S += sb[cb] * __expf(mb[cb] - M);
        sm_m[tid] = M;
        sm_li[tid] = 1.0f / S;
    }
    __syncthreads();

    const uint32_t abase[2] = { smem_u32(&As[0][0]), smem_u32(&As[1][0]) };
    const uint32_t bbase[2] = { smem_u32(&Bs[0][0]), smem_u32(&Bs[1][0]) };

    const int lrow8 = ((lane >> 3) & 1) * 8 + (lane & 7);
    const int ljc   = lane >> 4;
    uint32_t aoff[2][4], boff[2][2];
#pragma unroll
    for (int kkc = 0; kkc < 2; kkc++) {
#pragma unroll
        for (int i = 0; i < 4; i++)
            aoff[kkc][i] = frag_off(wr + i * 16 + lrow8, kkc * 2 + ljc);
#pragma unroll
        for (int p = 0; p < 2; p++)
            boff[kkc][p] = frag_off(wc + p * 16 + lrow8, kkc * 2 + ljc);
    }

    float acc[4][4][4] = {};

    const int srow = tid;
    float* Ap = A + (size_t)(m0 + srow) * SEQ;
    const float mr = sm_m[srow];
    const float li = sm_li[srow];
    const int schunkx = (srow >> 3) & 3;
    const int bk  = tid >> 4;            // 0..7
    const int bnc = (tid & 15) * 4;      // 0..60

    float4 av[4], bvv[2];
    auto ldtile = [&](int kt) {
#pragma unroll
        for (int j = 0; j < 4; j++)
            av[j] = *(const float4*)(Ap + kt * 16 + j * 4);
#pragma unroll
        for (int i = 0; i < 2; i++)
            bvv[i] = *(const float4*)(B + (size_t)(kt * 16 + bk + i * 8) * EMB + bnc);
    };
    auto sttile = [&](int buf, int kt) {
#pragma unroll
        for (int j = 0; j < 4; j++) {
            const int chunk = j ^ schunkx;
            const int col = kt * 16 + j * 4;
            const int4 mq = *(const int4*)(mrow + col);
            float4 p;
            p.x = __expf(((mq.x != 0) ? av[j].x : -1e20f) - mr) * li;
            p.y = __expf(((mq.y != 0) ? av[j].y : -1e20f) - mr) * li;
            p.z = __expf(((mq.z != 0) ? av[j].z : -1e20f) - mr) * li;
            p.w = __expf(((mq.w != 0) ? av[j].w : -1e20f) - mr) * li;
            uint4 at = make_uint4(f2tf(p.x), f2tf(p.y), f2tf(p.z), f2tf(p.w));
            *(uint4*)&As[buf][srow * SROW + chunk * 4] = at;
            __stcs((float4*)(Ap + col), p);
        }
#pragma unroll
        for (int i = 0; i < 2; i++) {
            const int k = bk + i * 8;
            const int jc = k >> 2, kw = k & 3;
            const float* v4 = (const float*)&bvv[i];
#pragma unroll
            for (int c = 0; c < 4; c++) {
                const int nrow = bnc + c;
                const int chunk = jc ^ ((nrow >> 3) & 3);
                Bs[buf][nrow * SROW + chunk * 4 + kw] = f2tf(v4[c]);
            }
        }
    };

    ldtile(0);
    sttile(0, 0);
    __syncthreads();

    const int NT = SEQ / 16;
#pragma unroll 1
    for (int kt = 0; kt < NT; kt++) {
        const int buf = kt & 1;
        if (kt + 1 < NT) ldtile(kt + 1);

#pragma unroll
        for (int kkc = 0; kkc < 2; kkc++) {
            unsigned af[4][4], bf[4][2];
#pragma unroll
            for (int mi = 0; mi < 4; mi++)
                ldsm4(af[mi][0], af[mi][1], af[mi][2], af[mi][3],
                      abase[buf] + aoff[kkc][mi]);
#pragma unroll
            for (int p = 0; p < 2; p++) {
                unsigned r0, r1, r2, r3;
                ldsm4(r0, r1, r2, r3, bbase[buf] + boff[kkc][p]);
                bf[2 * p][0] = r0; bf[2 * p + 1][0] = r1;
                bf[2 * p][1] = r2; bf[2 * p + 1][1] = r3;
            }
#pragma unroll
            for (int mi = 0; mi < 4; mi++)
#pragma unroll
                for (int ni = 0; ni < 4; ni++)
                    mma_tf32(acc[mi][ni], af[mi], bf[ni]);
        }

        if (kt + 1 < NT) sttile(buf ^ 1, kt + 1);
        __syncthreads();
    }

#pragma unroll
    for (int mi = 0; mi < 4; mi++) {
#pragma unroll
        for (int ni = 0; ni < 4; ni++) {
            const int row = m0 + wr + mi * 16 + g;
            const int col = wc + ni * 8 + t * 2;
            *(float2*)&C[(size_t)row * EMB + col] =
                make_float2(acc[mi][ni][0], acc[mi][ni][1]);
            *(float2*)&C[(size_t)(row + 8) * EMB + col] =
                make_float2(acc[mi][ni][2], acc[mi][ni][3]);
        }
    }
}

// ---------------------------------------------------------------------------
extern "C" void kernel_launch(void* const* d_in, const int* in_sizes, int n_in,
                              void* d_out, int out_size)
{
    const float* value = (const float*)d_in[0];
    const float* key_  = (const float*)d_in[1];
    const float* query = (const float*)d_in[2];
    const int*   mask  = (const int*)d_in[3];
    const float* Wv    = (const float*)d_in[4];
    const float* Wk    = (const float*)d_in[5];
    const float* Wq    = (const float*)d_in[6];
    const float* Wo    = (const float*)d_in[7];
    const float* bo    = (const float*)d_in[8];

    float* out = (float*)d_out;                 // [8,1024,1024]
    float* att = out + OUT_ELEMS;               // [8,16,1024,1024]

    float* op;
    cudaGetSymbolAddress((void**)&op, g_O);

    dim3 blk(128);

    qkv_proj<<<dim3(EMB / 128, ROWS / 128, 3), blk>>>(query, key_, value, Wq, Wk, Wv);
    energy_stats<<<dim3(SEQ / 128, SEQ / 128, NB * HEADS), blk>>>(att, mask);
    attv_fused<<<dim3(1, SEQ / 128, NB * HEADS), blk>>>(att, mask);
    proj_tf32<<<dim3(EMB / 128, ROWS / 128), blk>>>(op, Wo, out, bo);
}